// round 14
// baseline (speedup 1.0000x reference)
#include <cuda_runtime.h>
#include <cuda_fp16.h>
#include <math.h>
#include <stdint.h>

// ---------------------------------------------------------------------------
// Problem constants
// ---------------------------------------------------------------------------
#define B_SZ      8192
#define IN_DIM    7056
#define KPAD      7104
#define NC        221           // ceil(7056/32); last chunk half-valid
#define H1        512
#define FEAT      256
#define NQ        8
#define NLAYERS   3
#define HID       128
#define NACT      6

// GEMM1: two independent 8-warp groups per CTA, each 128x128 output tile.
// fp16 2-pass split: D = X16*Whi + X16*Wlo, X converted in-registers from fp32.
// Per-group stage: [A32 128x160B][Bhi 8K][Blo 8K] = 36KB, 3 stages.
#define BM        128
#define BN        256
#define BK        32
#define ROWB      64
#define A32STR    160
#define ASZ       (128 * A32STR)      // 20480
#define STG       (ASZ + 16384)       // 36864
#define NSTAGE    3
#define GRP       (NSTAGE * STG)      // 110592 per group
#define W2OFF     (2 * GRP)           // 221184
#define SMEM_G    (W2OFF + 8192)      // 229376

// ---------------------------------------------------------------------------
// Device scratch (no allocations allowed)
// ---------------------------------------------------------------------------
__device__ float  g_f8pre[B_SZ * NQ];             // pre-tanh feats8 accumulator
__device__ float2 g_gates[NLAYERS * NQ * 4];      // fused RZ*RY*RX
__device__ __half g_wthi[(size_t)H1 * KPAD];      // W^T hi: [n][k]
__device__ __half g_wtlo[(size_t)H1 * KPAD];      // W^T lo

// ---------------------------------------------------------------------------
// Helpers
// ---------------------------------------------------------------------------
__device__ __forceinline__ float2 cmul(float2 a, float2 b) {
    return make_float2(a.x * b.x - a.y * b.y, a.x * b.y + a.y * b.x);
}
__device__ __forceinline__ float2 cmadd2(float2 ga, float2 x, float2 gb, float2 y) {
    float re = ga.x * x.x - ga.y * x.y + gb.x * y.x - gb.y * y.y;
    float im = ga.x * x.y + ga.y * x.x + gb.x * y.y + gb.y * y.x;
    return make_float2(re, im);
}

__device__ __forceinline__ uint32_t s2u(const void* p) {
    uint32_t a;
    asm("{ .reg .u64 t; cvta.to.shared.u64 t, %1; cvt.u32.u64 %0, t; }"
        : "=r"(a) : "l"(p));
    return a;
}

__device__ __forceinline__ void ldsm_x4(uint32_t* r, uint32_t addr) {
    asm volatile("ldmatrix.sync.aligned.m8n8.x4.shared.b16 {%0,%1,%2,%3}, [%4];"
        : "=r"(r[0]), "=r"(r[1]), "=r"(r[2]), "=r"(r[3]) : "r"(addr));
}

__device__ __forceinline__ uint32_t lds64_cvt(uint32_t addr) {
    float2 v;
    asm volatile("ld.shared.v2.f32 {%0,%1}, [%2];"
                 : "=f"(v.x), "=f"(v.y) : "r"(addr));
    uint32_t h;
    asm volatile("cvt.rn.f16x2.f32 %0, %1, %2;" : "=r"(h) : "f"(v.y), "f"(v.x));
    return h;                         // lo = v.x (even k), hi = v.y (odd k)
}

__device__ __forceinline__ void mma_f16(float* c, const uint32_t* a,
                                        const uint32_t* b) {
    asm volatile(
        "mma.sync.aligned.m16n8k16.row.col.f32.f16.f16.f32 "
        "{%0,%1,%2,%3},{%4,%5,%6,%7},{%8,%9},{%0,%1,%2,%3};"
        : "+f"(c[0]), "+f"(c[1]), "+f"(c[2]), "+f"(c[3])
        : "r"(a[0]), "r"(a[1]), "r"(a[2]), "r"(a[3]), "r"(b[0]), "r"(b[1]));
}

#define BFLY2(v, m) do { \
    (v).x = __shfl_xor_sync(0xffffffffu, (v).x, (m)); \
    (v).y = __shfl_xor_sync(0xffffffffu, (v).y, (m)); \
} while (0)

// ---------------------------------------------------------------------------
// Kernel 0: fuse per-(layer,qubit) RX,RY,RZ into one complex 2x2 gate.
// ---------------------------------------------------------------------------
__global__ void fuse_gates_kernel(const float* __restrict__ qp) {
    int t = threadIdx.x;
    if (t >= NLAYERS * NQ) return;
    float a = qp[t * 3 + 0], b = qp[t * 3 + 1], c = qp[t * 3 + 2];
    float sa, ca, sb, cb, sc, cc;
    sincosf(0.5f * a, &sa, &ca);
    sincosf(0.5f * b, &sb, &cb);
    sincosf(0.5f * c, &sc, &cc);
    float2 m00 = make_float2( cb * ca,  sb * sa);
    float2 m01 = make_float2(-sb * ca, -cb * sa);
    float2 m10 = make_float2( sb * ca, -cb * sa);
    float2 m11 = make_float2( cb * ca, -sb * sa);
    float2 e0 = make_float2(cc, -sc);
    float2 e1 = make_float2(cc,  sc);
    g_gates[t * 4 + 0] = cmul(e0, m00);
    g_gates[t * 4 + 1] = cmul(e0, m01);
    g_gates[t * 4 + 2] = cmul(e1, m10);
    g_gates[t * 4 + 3] = cmul(e1, m11);
}

// ---------------------------------------------------------------------------
// Conversion: W [7056][512] fp32 -> transposed fp16 hi/lo [512][KPAD]
// ---------------------------------------------------------------------------
__global__ void convert_w_kernel(const float* __restrict__ W) {
    __shared__ float t[32][33];
    int k0 = blockIdx.x * 32, n0 = blockIdx.y * 32;
    int tx = threadIdx.x, ty = threadIdx.y;
#pragma unroll
    for (int r = 0; r < 32; r += 8) {
        int k = k0 + ty + r;
        t[ty + r][tx] = (k < IN_DIM) ? W[(size_t)k * H1 + n0 + tx] : 0.f;
    }
    __syncthreads();
#pragma unroll
    for (int r = 0; r < 32; r += 8) {
        int n = n0 + ty + r;
        int k = k0 + tx;
        float v = t[tx][ty + r];
        __half h = __float2half_rn(v);
        g_wthi[(size_t)n * KPAD + k] = h;
        g_wtlo[(size_t)n * KPAD + k] = __float2half_rn(v - __half2float(h));
    }
}

// ---------------------------------------------------------------------------
// GEMM1: mma.sync fp16 2-pass, two decoupled 8-warp groups, fp32 A staged in
// smem (160B stride, conflict-free LDS.64) and converted per-fragment in regs.
// Fused epilogue: partial feats8 = relu(acc+b1) @ W2[:, :8] -> atomicAdd.
// B uses swizzled 64B rows (slot = c16 ^ ((row>>1)&3)).
// ---------------------------------------------------------------------------
__device__ __forceinline__ uint32_t sw_off(int row, int c16) {
    return (uint32_t)row * ROWB + (uint32_t)((c16 ^ ((row >> 1) & 3)) << 4);
}

__device__ __forceinline__ void load_chunk_g(const float* __restrict__ X,
                                             uint32_t stage, int bm, int bng,
                                             int c, int gtid) {
    const int kelem = c * BK;
    // A: 1024 granules of fp32 X (128 rows x 128B) into 160B-stride rows
#pragma unroll
    for (int j = 0; j < 4; j++) {
        int idx = gtid + j * 256;
        int row = idx >> 3, gc = idx & 7;
        int kk = kelem + gc * 4;
        if (kk > IN_DIM - 4) kk = IN_DIM - 4;           // clamp (tail zeroed)
        const char* src = (const char*)(X + (size_t)(bm + row) * IN_DIM + kk);
        uint32_t dst = stage + (uint32_t)row * A32STR + (uint32_t)(gc << 4);
        asm volatile("cp.async.cg.shared.global [%0], [%1], 16;"
                     :: "r"(dst), "l"(src));
    }
    // B: 2 splits x 512 granules (fp16, swizzled)
#pragma unroll
    for (int j = 0; j < 4; j++) {
        int id = gtid + j * 256;
        int split = id >> 9, idx = id & 511;
        int row = idx >> 2, c16 = idx & 3;
        const __half* base = split ? g_wtlo : g_wthi;
        const char* src = (const char*)(base + (size_t)(bng + row) * KPAD
                                        + kelem + c16 * 8);
        uint32_t dst = stage + ASZ + (uint32_t)split * 8192u + sw_off(row, c16);
        asm volatile("cp.async.cg.shared.global [%0], [%1], 16;"
                     :: "r"(dst), "l"(src));
    }
}

__global__ __launch_bounds__(512, 1)
void gemm1_mma_kernel(const float* __restrict__ X,
                      const float* __restrict__ bias,
                      const float* __restrict__ W2) {
    extern __shared__ char smem[];
    const uint32_t sb = s2u(smem);
    const int tid = threadIdx.x, wid = tid >> 5, lane = tid & 31;
    const int g = wid >> 3;               // group 0/1
    const int gtid = tid & 255;
    const uint32_t gbase = sb + (uint32_t)g * GRP;
    const int bm = blockIdx.y * BM;
    const int bng = blockIdx.x * BN + g * 128;
    const int wg = wid & 7;
    const int wm = (wg >> 1) * 32;        // warp row within group tile
    const int wn = (wg & 1) * 64;         // warp col within group tile
    const int barid = g + 1;

    // Each group loads its own W2 slice [128][8] (visible after first bar.sync)
    {
        float* w2s = (float*)(smem + W2OFF) + g * 1024;
        for (int i = gtid; i < 1024; i += 256) {
            int kk = i >> 3, j = i & 7;
            w2s[i] = W2[(size_t)(bng + kk) * FEAT + j];
        }
    }

    float acc[2][8][4];
#pragma unroll
    for (int mt = 0; mt < 2; mt++)
#pragma unroll
        for (int nt = 0; nt < 8; nt++)
#pragma unroll
            for (int q = 0; q < 4; q++) acc[mt][nt][q] = 0.f;

    // prologue: chunks 0,1 into stages 0,1
    load_chunk_g(X, gbase + 0 * STG, bm, bng, 0, gtid);
    asm volatile("cp.async.commit_group;" ::: "memory");
    load_chunk_g(X, gbase + 1 * STG, bm, bng, 1, gtid);
    asm volatile("cp.async.commit_group;" ::: "memory");

    const int lr = lane & 15;
    const int lc = lane >> 4;
    const int g4 = lane >> 2, t4 = lane & 3;

    int cur = 0;
    for (int c = 0; c < NC; c++) {
        asm volatile("cp.async.wait_group 1;" ::: "memory");
        asm volatile("bar.sync %0, %1;" :: "r"(barid), "r"(256) : "memory");
        int ld = cur + 2; if (ld >= NSTAGE) ld -= NSTAGE;
        if (c + 2 < NC)
            load_chunk_g(X, gbase + (uint32_t)ld * STG, bm, bng, c + 2, gtid);
        asm volatile("cp.async.commit_group;" ::: "memory");

        const uint32_t aBase = gbase + (uint32_t)cur * STG;
        const uint32_t bBase = aBase + ASZ;
        const bool lastc = (c == NC - 1);
#pragma unroll
        for (int kk = 0; kk < 2; kk++) {
            const int c16 = kk * 2 + lc;
            uint32_t ah[8], bh[16];
            // A fragments: fp32 LDS.64 + cvt (conflict-free: banks 8r+2t)
            if (lastc && kk == 1) {
#pragma unroll
                for (int i = 0; i < 8; i++) ah[i] = 0u;
            } else {
#pragma unroll
                for (int mt = 0; mt < 2; mt++) {
                    uint32_t r0 = aBase + (uint32_t)(wm + mt * 16 + g4) * A32STR;
                    uint32_t r1 = r0 + 8u * A32STR;
                    uint32_t p0 = (uint32_t)(kk * 8 + t4) * 8u;
                    ah[mt * 4 + 0] = lds64_cvt(r0 + p0);
                    ah[mt * 4 + 1] = lds64_cvt(r1 + p0);
                    ah[mt * 4 + 2] = lds64_cvt(r0 + p0 + 32u);
                    ah[mt * 4 + 3] = lds64_cvt(r1 + p0 + 32u);
                }
            }
#pragma unroll
            for (int bt = 0; bt < 4; bt++)
                ldsm_x4(&bh[bt * 4], bBase + sw_off(wn + bt * 16 + lr, c16));
            // pass 1: X * Whi
#pragma unroll
            for (int mt = 0; mt < 2; mt++)
#pragma unroll
                for (int nt = 0; nt < 8; nt++) {
                    uint32_t bp[2] = { bh[(nt >> 1) * 4 + (nt & 1)],
                                       bh[(nt >> 1) * 4 + 2 + (nt & 1)] };
                    mma_f16(acc[mt][nt], &ah[mt * 4], bp);
                }
            // pass 2: X * Wlo
            {
                uint32_t bl[16];
#pragma unroll
                for (int bt = 0; bt < 4; bt++)
                    ldsm_x4(&bl[bt * 4], bBase + 8192u
                                         + sw_off(wn + bt * 16 + lr, c16));
#pragma unroll
                for (int mt = 0; mt < 2; mt++)
#pragma unroll
                    for (int nt = 0; nt < 8; nt++) {
                        uint32_t bp[2] = { bl[(nt >> 1) * 4 + (nt & 1)],
                                           bl[(nt >> 1) * 4 + 2 + (nt & 1)] };
                        mma_f16(acc[mt][nt], &ah[mt * 4], bp);
                    }
            }
        }
        cur++; if (cur >= NSTAGE) cur = 0;
    }

    // Fused epilogue: partial feats8 = relu(acc+bias) @ W2slice -> atomicAdd
    {
        const float* w2l = (const float*)(smem + W2OFF) + g * 1024;
        const int colL = wn + (lane & 3) * 2;
        float part[4][8];
#pragma unroll
        for (int r4 = 0; r4 < 4; r4++)
#pragma unroll
            for (int j = 0; j < 8; j++) part[r4][j] = 0.f;

#pragma unroll
        for (int nt = 0; nt < 8; nt++) {
            int c0 = colL + nt * 8;
            float2 bv = *(const float2*)(bias + bng + c0);
            float4 wa = *(const float4*)(w2l + c0 * 8);
            float4 wb = *(const float4*)(w2l + c0 * 8 + 4);
            float4 wc = *(const float4*)(w2l + (c0 + 1) * 8);
            float4 wd = *(const float4*)(w2l + (c0 + 1) * 8 + 4);
#pragma unroll
            for (int mt = 0; mt < 2; mt++) {
                float h0 = fmaxf(acc[mt][nt][0] + bv.x, 0.f);
                float h1 = fmaxf(acc[mt][nt][1] + bv.y, 0.f);
                float h2 = fmaxf(acc[mt][nt][2] + bv.x, 0.f);
                float h3 = fmaxf(acc[mt][nt][3] + bv.y, 0.f);
                float* p0 = part[mt * 2 + 0];
                float* p1 = part[mt * 2 + 1];
                p0[0] += h0 * wa.x + h1 * wc.x;
                p0[1] += h0 * wa.y + h1 * wc.y;
                p0[2] += h0 * wa.z + h1 * wc.z;
                p0[3] += h0 * wa.w + h1 * wc.w;
                p0[4] += h0 * wb.x + h1 * wd.x;
                p0[5] += h0 * wb.y + h1 * wd.y;
                p0[6] += h0 * wb.z + h1 * wd.z;
                p0[7] += h0 * wb.w + h1 * wd.w;
                p1[0] += h2 * wa.x + h3 * wc.x;
                p1[1] += h2 * wa.y + h3 * wc.y;
                p1[2] += h2 * wa.z + h3 * wc.z;
                p1[3] += h2 * wa.w + h3 * wc.w;
                p1[4] += h2 * wb.x + h3 * wd.x;
                p1[5] += h2 * wb.y + h3 * wd.y;
                p1[6] += h2 * wb.z + h3 * wd.z;
                p1[7] += h2 * wb.w + h3 * wd.w;
            }
        }
        const int rbase = bm + wm + (lane >> 2);
#pragma unroll
        for (int r4 = 0; r4 < 4; r4++) {
            int r = rbase + r4 * 8;
#pragma unroll
            for (int j = 0; j < 8; j++)
                atomicAdd(&g_f8pre[r * NQ + j], part[r4][j]);
        }
    }
}

// ---------------------------------------------------------------------------
// Kernel 2: fused tanh + quantum sim + post MLP. One warp per sample.
// ---------------------------------------------------------------------------
__global__ __launch_bounds__(256, 2)
void qpost_kernel(const float* __restrict__ b2q,
                  const float* __restrict__ W1, const float* __restrict__ b1,
                  const float* __restrict__ W2, const float* __restrict__ b2,
                  const float* __restrict__ W3, const float* __restrict__ b3,
                  float* __restrict__ out) {
    __shared__ float2 gs[NLAYERS * NQ * 4];
    __shared__ float w1s[NQ * HID];
    __shared__ float b1s[HID];
    __shared__ float w2s[HID * 64];
    __shared__ float b2s[64];
    __shared__ float w3s[64 * NACT];
    __shared__ float b3s[NACT];
    __shared__ float h2s[8][HID];
    __shared__ float h3s[8][64];

    const int tid = threadIdx.x;
    const int warp = tid >> 5, lane = tid & 31;
    if (tid < NLAYERS * NQ * 4) gs[tid] = g_gates[tid];
    for (int i = tid; i < NQ * HID; i += 256) w1s[i] = W1[i];
    if (tid < HID) b1s[tid] = b1[tid];
    for (int i = tid; i < HID * 64; i += 256) w2s[i] = W2[i];
    if (tid < 64) b2s[tid] = b2[tid];
    for (int i = tid; i < 64 * NACT; i += 256) w3s[i] = W3[i];
    if (tid < NACT) b3s[tid] = b3[tid];
    __syncthreads();

    const int b = blockIdx.x * 8 + warp;

    // feats8 = tanh(g_f8pre + b2q)
    float f = tanhf(g_f8pre[b * NQ + (lane & 7)] + b2q[lane & 7]);
    float a0[NQ], a1[NQ];
#pragma unroll
    for (int i = 0; i < NQ; i++) {
        float th = __shfl_sync(0xffffffffu, f, i) * 1.57079632679489662f;
        float s, c;
        sincosf(th, &s, &c);
        const float r = 0.70710678118654752f;
        a0[i] = (c - s) * r;
        a1[i] = (c + s) * r;
    }
    float2 a[8];
#pragma unroll
    for (int r8 = 0; r8 < 8; r8++) {
        int idx = (r8 << 5) | lane;
        float p = 1.f;
#pragma unroll
        for (int i = 0; i < NQ; i++)
            p *= ((idx >> (7 - i)) & 1) ? a1[i] : a0[i];
        a[r8] = make_float2(p, 0.f);
    }

#pragma unroll 1
    for (int layer = 0; layer < NLAYERS; layer++) {
        { float2 t = a[4]; a[4] = a[6]; a[6] = t;
          t = a[5]; a[5] = a[7]; a[7] = t; }
#pragma unroll
        for (int r8 = 1; r8 < 8; r8 += 2) BFLY2(a[r8], 16);
        { bool cb = (lane >> 3) & 1;
#pragma unroll
          for (int r8 = 0; r8 < 8; r8++) {
              float2 t = a[r8]; BFLY2(t, 4); if (cb) a[r8] = t;
          } }
        { bool cb = (lane >> 1) & 1;
#pragma unroll
          for (int r8 = 0; r8 < 8; r8++) {
              float2 t = a[r8]; BFLY2(t, 1); if (cb) a[r8] = t;
          } }
        { float2 t = a[2]; a[2] = a[3]; a[3] = t;
          t = a[6]; a[6] = a[7]; a[7] = t; }
        { bool cb = (lane >> 4) & 1;
#pragma unroll
          for (int r8 = 0; r8 < 8; r8++) {
              float2 t = a[r8]; BFLY2(t, 8); if (cb) a[r8] = t;
          } }
        { bool cb = (lane >> 2) & 1;
#pragma unroll
          for (int r8 = 0; r8 < 8; r8++) {
              float2 t = a[r8]; BFLY2(t, 2); if (cb) a[r8] = t;
          } }

        const float2* gl = &gs[layer * NQ * 4];
#pragma unroll
        for (int i = 0; i < NQ; i++) {
            const int p = 7 - i;
            float2 g0 = gl[i * 4 + 0], g1 = gl[i * 4 + 1];
            float2 g2 = gl[i * 4 + 2], g3 = gl[i * 4 + 3];
            if (p >= 5) {
                const int rb = 1 << (p - 5);
#pragma unroll
                for (int r0 = 0; r0 < 8; r0++) {
                    if (r0 & rb) continue;
                    int r1 = r0 | rb;
                    float2 x = a[r0], y = a[r1];
                    a[r0] = cmadd2(g0, x, g1, y);
                    a[r1] = cmadd2(g2, x, g3, y);
                }
            } else {
                const int mask = 1 << p;
                const int bit = (lane >> p) & 1;
                float2 ga = bit ? g3 : g0;
                float2 gb = bit ? g2 : g1;
#pragma unroll
                for (int r8 = 0; r8 < 8; r8++) {
                    float2 o = a[r8]; BFLY2(o, mask);
                    a[r8] = cmadd2(ga, a[r8], gb, o);
                }
            }
        }
    }

    // Measurement
    float pr[8];
#pragma unroll
    for (int r8 = 0; r8 < 8; r8++) pr[r8] = a[r8].x * a[r8].x + a[r8].y * a[r8].y;

    float ev[NQ];
    ev[0] = pr[0] + pr[1] + pr[2] + pr[3] - pr[4] - pr[5] - pr[6] - pr[7];
    ev[1] = pr[0] + pr[1] - pr[2] - pr[3] + pr[4] + pr[5] - pr[6] - pr[7];
    ev[2] = pr[0] - pr[1] + pr[2] - pr[3] + pr[4] - pr[5] + pr[6] - pr[7];
    float T = pr[0] + pr[1] + pr[2] + pr[3] + pr[4] + pr[5] + pr[6] + pr[7];
#pragma unroll
    for (int i = 3; i < NQ; i++) {
        int p = 7 - i;
        ev[i] = ((lane >> p) & 1) ? -T : T;
    }
#pragma unroll
    for (int off = 16; off > 0; off >>= 1)
#pragma unroll
        for (int i = 0; i < NQ; i++)
            ev[i] += __shfl_xor_sync(0xffffffffu, ev[i], off);

    // Post MLP directly on ev (broadcast across lanes)
#pragma unroll
    for (int jj = 0; jj < 4; jj++) {
        int j = lane + jj * 32;
        float s = b1s[j];
#pragma unroll
        for (int i = 0; i < NQ; i++) s = fmaf(ev[i], w1s[i * HID + j], s);
        h2s[warp][j] = fmaxf(s, 0.f);
    }
    __syncwarp();

#pragma unroll
    for (int jj = 0; jj < 2; jj++) {
        int j = lane + jj * 32;
        float s = b2s[j];
#pragma unroll
        for (int k = 0; k < HID; k++) s = fmaf(h2s[warp][k], w2s[k * 64 + j], s);
        h3s[warp][j] = fmaxf(s, 0.f);
    }
    __syncwarp();

    if (lane < NACT) {
        float s = b3s[lane];
#pragma unroll
        for (int k = 0; k < 64; k++) s = fmaf(h3s[warp][k], w3s[k * NACT + lane], s);
        out[b * NACT + lane] = s;
    }
}

// ---------------------------------------------------------------------------
// Launcher
// ---------------------------------------------------------------------------
extern "C" void kernel_launch(void* const* d_in, const int* in_sizes, int n_in,
                              void* d_out, int out_size) {
    const float* x       = (const float*)d_in[0];
    const float* pre_W1  = (const float*)d_in[1];
    const float* pre_b1  = (const float*)d_in[2];
    const float* pre_W2  = (const float*)d_in[3];
    const float* pre_b2  = (const float*)d_in[4];
    const float* qparams = (const float*)d_in[5];
    const float* post_W1 = (const float*)d_in[6];
    const float* post_b1 = (const float*)d_in[7];
    const float* post_W2 = (const float*)d_in[8];
    const float* post_b2 = (const float*)d_in[9];
    const float* post_W3 = (const float*)d_in[10];
    const float* post_b3 = (const float*)d_in[11];
    float* out = (float*)d_out;

    static int init_done = 0;
    static void* f8_addr = nullptr;
    if (!init_done) {
        cudaFuncSetAttribute(gemm1_mma_kernel,
                             cudaFuncAttributeMaxDynamicSharedMemorySize, SMEM_G);
        cudaGetSymbolAddress(&f8_addr, g_f8pre);
        init_done = 1;
    }

    fuse_gates_kernel<<<1, 32>>>(qparams);
    convert_w_kernel<<<dim3(KPAD / 32, H1 / 32), dim3(32, 8)>>>(pre_W1);
    cudaMemsetAsync(f8_addr, 0, B_SZ * NQ * sizeof(float));

    gemm1_mma_kernel<<<dim3(2, 64), 512, SMEM_G>>>(x, pre_b1, pre_W2);

    qpost_kernel<<<B_SZ / 8, 256>>>(pre_b2, post_W1, post_b1, post_W2, post_b2,
                                    post_W3, post_b3, out);
}

// round 15
// speedup vs baseline: 1.0186x; 1.0186x over previous
#include <cuda_runtime.h>
#include <cuda_fp16.h>
#include <math.h>
#include <stdint.h>

// ---------------------------------------------------------------------------
// Problem constants
// ---------------------------------------------------------------------------
#define B_SZ      8192
#define IN_DIM    7056
#define KPAD      7104
#define NC        222          // chunks of 32 (KPAD/32; X padded with zeros)
#define H1        512
#define FEAT      256
#define NQ        8
#define NLAYERS   3
#define HID       128
#define NACT      6

// GEMM1: two independent 8-warp groups per CTA, each 128x128 output tile.
// fp16 2-pass split:  D = X16*Whi + X16*Wlo  (fp32 accumulate)
// Per-group stage: [A 8K][Bhi 8K][Blo 8K] = 24KB, 4 stages.
#define BM        128
#define BN        256
#define BK        32
#define ROWB      64
#define STG       24576
#define NSTAGE    4
#define GRP       (NSTAGE * STG)  // 98304 per group
#define W2OFF     (2 * GRP)       // 196608
#define SMEM_G    (W2OFF + 8192)  // 204800

// qpost: blocks x iterations covering B_SZ/8 sample groups
#define QBLOCKS   256
#define QITER     4

// ---------------------------------------------------------------------------
// Device scratch (no allocations allowed)
// ---------------------------------------------------------------------------
__device__ float  g_f8pre[B_SZ * NQ];             // pre-tanh feats8 accumulator
__device__ float2 g_gates[NLAYERS * NQ * 4];      // fused RZ*RY*RX
__device__ __half g_xh[(size_t)B_SZ * KPAD];      // X in fp16
__device__ __half g_wthi[(size_t)H1 * KPAD];      // W^T hi: [n][k]
__device__ __half g_wtlo[(size_t)H1 * KPAD];      // W^T lo

// ---------------------------------------------------------------------------
// Helpers
// ---------------------------------------------------------------------------
__device__ __forceinline__ float2 cmul(float2 a, float2 b) {
    return make_float2(a.x * b.x - a.y * b.y, a.x * b.y + a.y * b.x);
}
__device__ __forceinline__ float2 cmadd2(float2 ga, float2 x, float2 gb, float2 y) {
    float re = ga.x * x.x - ga.y * x.y + gb.x * y.x - gb.y * y.y;
    float im = ga.x * x.y + ga.y * x.x + gb.x * y.y + gb.y * y.x;
    return make_float2(re, im);
}

__device__ __forceinline__ uint32_t s2u(const void* p) {
    uint32_t a;
    asm("{ .reg .u64 t; cvta.to.shared.u64 t, %1; cvt.u32.u64 %0, t; }"
        : "=r"(a) : "l"(p));
    return a;
}

__device__ __forceinline__ void ldsm_x4(uint32_t* r, uint32_t addr) {
    asm volatile("ldmatrix.sync.aligned.m8n8.x4.shared.b16 {%0,%1,%2,%3}, [%4];"
        : "=r"(r[0]), "=r"(r[1]), "=r"(r[2]), "=r"(r[3]) : "r"(addr));
}

__device__ __forceinline__ void mma_f16(float* c, const uint32_t* a,
                                        const uint32_t* b) {
    asm volatile(
        "mma.sync.aligned.m16n8k16.row.col.f32.f16.f16.f32 "
        "{%0,%1,%2,%3},{%4,%5,%6,%7},{%8,%9},{%0,%1,%2,%3};"
        : "+f"(c[0]), "+f"(c[1]), "+f"(c[2]), "+f"(c[3])
        : "r"(a[0]), "r"(a[1]), "r"(a[2]), "r"(a[3]), "r"(b[0]), "r"(b[1]));
}

#define BFLY2(v, m) do { \
    (v).x = __shfl_xor_sync(0xffffffffu, (v).x, (m)); \
    (v).y = __shfl_xor_sync(0xffffffffu, (v).y, (m)); \
} while (0)

// ---------------------------------------------------------------------------
// Kernel 0: fuse per-(layer,qubit) RX,RY,RZ into one complex 2x2 gate.
// ---------------------------------------------------------------------------
__global__ void fuse_gates_kernel(const float* __restrict__ qp) {
    int t = threadIdx.x;
    if (t >= NLAYERS * NQ) return;
    float a = qp[t * 3 + 0], b = qp[t * 3 + 1], c = qp[t * 3 + 2];
    float sa, ca, sb, cb, sc, cc;
    sincosf(0.5f * a, &sa, &ca);
    sincosf(0.5f * b, &sb, &cb);
    sincosf(0.5f * c, &sc, &cc);
    float2 m00 = make_float2( cb * ca,  sb * sa);
    float2 m01 = make_float2(-sb * ca, -cb * sa);
    float2 m10 = make_float2( sb * ca, -cb * sa);
    float2 m11 = make_float2( cb * ca, -sb * sa);
    float2 e0 = make_float2(cc, -sc);
    float2 e1 = make_float2(cc,  sc);
    g_gates[t * 4 + 0] = cmul(e0, m00);
    g_gates[t * 4 + 1] = cmul(e0, m01);
    g_gates[t * 4 + 2] = cmul(e1, m10);
    g_gates[t * 4 + 3] = cmul(e1, m11);
}

// ---------------------------------------------------------------------------
// Conversion: X fp32 -> fp16 (K padded to KPAD with zeros)
// ---------------------------------------------------------------------------
__global__ __launch_bounds__(256)
void convert_x_kernel(const float* __restrict__ X) {
    int row = blockIdx.x;
    const float4* src = (const float4*)(X + (size_t)row * IN_DIM);
    __half2* dst = (__half2*)(g_xh + (size_t)row * KPAD);
    for (int k4 = threadIdx.x; k4 < KPAD / 4; k4 += 256) {
        float4 v = (k4 < IN_DIM / 4) ? src[k4] : make_float4(0.f, 0.f, 0.f, 0.f);
        dst[k4 * 2 + 0] = __floats2half2_rn(v.x, v.y);
        dst[k4 * 2 + 1] = __floats2half2_rn(v.z, v.w);
    }
}

// ---------------------------------------------------------------------------
// Conversion: W [7056][512] fp32 -> transposed fp16 hi/lo [512][KPAD]
// ---------------------------------------------------------------------------
__global__ void convert_w_kernel(const float* __restrict__ W) {
    __shared__ float t[32][33];
    int k0 = blockIdx.x * 32, n0 = blockIdx.y * 32;
    int tx = threadIdx.x, ty = threadIdx.y;
#pragma unroll
    for (int r = 0; r < 32; r += 8) {
        int k = k0 + ty + r;
        t[ty + r][tx] = (k < IN_DIM) ? W[(size_t)k * H1 + n0 + tx] : 0.f;
    }
    __syncthreads();
#pragma unroll
    for (int r = 0; r < 32; r += 8) {
        int n = n0 + ty + r;
        int k = k0 + tx;
        float v = t[tx][ty + r];
        __half h = __float2half_rn(v);
        g_wthi[(size_t)n * KPAD + k] = h;
        g_wtlo[(size_t)n * KPAD + k] = __float2half_rn(v - __half2float(h));
    }
}

// ---------------------------------------------------------------------------
// GEMM1: mma.sync fp16 2-pass (X*Whi + X*Wlo), two decoupled 8-warp groups.
// Each group: 128x128 output, own 4-stage pipeline, own named barrier.
// Fused epilogue: partial feats8 = relu(acc+b1) @ W2[:, :8] -> atomicAdd.
// Swizzled 64B smem rows (slot = c16 ^ ((row>>1)&3)).
// ---------------------------------------------------------------------------
__device__ __forceinline__ uint32_t sw_off(int row, int c16) {
    return (uint32_t)row * ROWB + (uint32_t)((c16 ^ ((row >> 1) & 3)) << 4);
}

__device__ __forceinline__ void load_chunk_g(uint32_t stage, int bm, int bng,
                                             int c, int gtid) {
    const size_t kelem = (size_t)c * BK;
#pragma unroll
    for (int j = 0; j < 2; j++) {         // A: 512 granules (fp16 X)
        int idx = gtid + j * 256;
        int row = idx >> 2, c16 = idx & 3;
        const char* src = (const char*)(g_xh + (size_t)(bm + row) * KPAD + kelem
                                        + c16 * 8);
        uint32_t dst = stage + sw_off(row, c16);
        asm volatile("cp.async.cg.shared.global [%0], [%1], 16;"
                     :: "r"(dst), "l"(src));
    }
#pragma unroll
    for (int j = 0; j < 4; j++) {         // B: 2 splits x 512 granules
        int id = gtid + j * 256;
        int split = id >> 9, idx = id & 511;
        int row = idx >> 2, c16 = idx & 3;
        const __half* base = split ? g_wtlo : g_wthi;
        const char* src = (const char*)(base + (size_t)(bng + row) * KPAD + kelem
                                        + c16 * 8);
        uint32_t dst = stage + 8192u + (uint32_t)split * 8192u + sw_off(row, c16);
        asm volatile("cp.async.cg.shared.global [%0], [%1], 16;"
                     :: "r"(dst), "l"(src));
    }
}

__global__ __launch_bounds__(512, 1)
void gemm1_mma_kernel(const float* __restrict__ bias,
                      const float* __restrict__ W2) {
    extern __shared__ char smem[];
    const uint32_t sb = s2u(smem);
    const int tid = threadIdx.x, wid = tid >> 5, lane = tid & 31;
    const int g = wid >> 3;               // group 0/1
    const int gtid = tid & 255;
    const uint32_t gbase = sb + (uint32_t)g * GRP;
    const int bm = blockIdx.y * BM;
    const int bng = blockIdx.x * BN + g * 128;
    const int wg = wid & 7;
    const int wm = (wg >> 1) * 32;        // warp row within group tile
    const int wn = (wg & 1) * 64;         // warp col within group tile
    const int barid = g + 1;

    // Each group loads its own W2 slice [128][8] (visible after first bar.sync)
    {
        float* w2s = (float*)(smem + W2OFF) + g * 1024;
        for (int i = gtid; i < 1024; i += 256) {
            int kk = i >> 3, j = i & 7;
            w2s[i] = W2[(size_t)(bng + kk) * FEAT + j];
        }
    }

    float acc[2][8][4];
#pragma unroll
    for (int mt = 0; mt < 2; mt++)
#pragma unroll
        for (int nt = 0; nt < 8; nt++)
#pragma unroll
            for (int q = 0; q < 4; q++) acc[mt][nt][q] = 0.f;

    // prologue: chunks 0,1 into stages 0,1
    load_chunk_g(gbase + 0 * STG, bm, bng, 0, gtid);
    asm volatile("cp.async.commit_group;" ::: "memory");
    load_chunk_g(gbase + 1 * STG, bm, bng, 1, gtid);
    asm volatile("cp.async.commit_group;" ::: "memory");

    const int lr = lane & 15;
    const int lc = lane >> 4;

    for (int c = 0; c < NC; c++) {
        asm volatile("cp.async.wait_group 1;" ::: "memory");
        asm volatile("bar.sync %0, %1;" :: "r"(barid), "r"(256) : "memory");
        if (c + 2 < NC)
            load_chunk_g(gbase + (uint32_t)((c + 2) & 3) * STG, bm, bng,
                         c + 2, gtid);
        asm volatile("cp.async.commit_group;" ::: "memory");

        const uint32_t aBase = gbase + (uint32_t)(c & 3) * STG;
        const uint32_t bBase = aBase + 8192u;
#pragma unroll
        for (int kk = 0; kk < 2; kk++) {
            const int c16 = kk * 2 + lc;
            uint32_t ah[8], bh[16];
#pragma unroll
            for (int mt = 0; mt < 2; mt++)
                ldsm_x4(&ah[mt * 4], aBase + sw_off(wm + mt * 16 + lr, c16));
#pragma unroll
            for (int bt = 0; bt < 4; bt++)
                ldsm_x4(&bh[bt * 4], bBase + sw_off(wn + bt * 16 + lr, c16));
            // pass 1: X * Whi
#pragma unroll
            for (int mt = 0; mt < 2; mt++)
#pragma unroll
                for (int nt = 0; nt < 8; nt++) {
                    uint32_t bp[2] = { bh[(nt >> 1) * 4 + (nt & 1)],
                                       bh[(nt >> 1) * 4 + 2 + (nt & 1)] };
                    mma_f16(acc[mt][nt], &ah[mt * 4], bp);
                }
            // pass 2: X * Wlo
            {
                uint32_t bl[16];
#pragma unroll
                for (int bt = 0; bt < 4; bt++)
                    ldsm_x4(&bl[bt * 4], bBase + 8192u
                                         + sw_off(wn + bt * 16 + lr, c16));
#pragma unroll
                for (int mt = 0; mt < 2; mt++)
#pragma unroll
                    for (int nt = 0; nt < 8; nt++) {
                        uint32_t bp[2] = { bl[(nt >> 1) * 4 + (nt & 1)],
                                           bl[(nt >> 1) * 4 + 2 + (nt & 1)] };
                        mma_f16(acc[mt][nt], &ah[mt * 4], bp);
                    }
            }
        }
    }

    // Fused epilogue: partial feats8 = relu(acc+bias) @ W2slice -> atomicAdd
    {
        const float* w2l = (const float*)(smem + W2OFF) + g * 1024;
        const int colL = wn + (lane & 3) * 2;
        float part[4][8];
#pragma unroll
        for (int r4 = 0; r4 < 4; r4++)
#pragma unroll
            for (int j = 0; j < 8; j++) part[r4][j] = 0.f;

#pragma unroll
        for (int nt = 0; nt < 8; nt++) {
            int c0 = colL + nt * 8;
            float2 bv = *(const float2*)(bias + bng + c0);
            float4 wa = *(const float4*)(w2l + c0 * 8);
            float4 wb = *(const float4*)(w2l + c0 * 8 + 4);
            float4 wc = *(const float4*)(w2l + (c0 + 1) * 8);
            float4 wd = *(const float4*)(w2l + (c0 + 1) * 8 + 4);
#pragma unroll
            for (int mt = 0; mt < 2; mt++) {
                float h0 = fmaxf(acc[mt][nt][0] + bv.x, 0.f);
                float h1 = fmaxf(acc[mt][nt][1] + bv.y, 0.f);
                float h2 = fmaxf(acc[mt][nt][2] + bv.x, 0.f);
                float h3 = fmaxf(acc[mt][nt][3] + bv.y, 0.f);
                float* p0 = part[mt * 2 + 0];
                float* p1 = part[mt * 2 + 1];
                p0[0] += h0 * wa.x + h1 * wc.x;
                p0[1] += h0 * wa.y + h1 * wc.y;
                p0[2] += h0 * wa.z + h1 * wc.z;
                p0[3] += h0 * wa.w + h1 * wc.w;
                p0[4] += h0 * wb.x + h1 * wd.x;
                p0[5] += h0 * wb.y + h1 * wd.y;
                p0[6] += h0 * wb.z + h1 * wd.z;
                p0[7] += h0 * wb.w + h1 * wd.w;
                p1[0] += h2 * wa.x + h3 * wc.x;
                p1[1] += h2 * wa.y + h3 * wc.y;
                p1[2] += h2 * wa.z + h3 * wc.z;
                p1[3] += h2 * wa.w + h3 * wc.w;
                p1[4] += h2 * wb.x + h3 * wd.x;
                p1[5] += h2 * wb.y + h3 * wd.y;
                p1[6] += h2 * wb.z + h3 * wd.z;
                p1[7] += h2 * wb.w + h3 * wd.w;
            }
        }
        const int rbase = bm + wm + (lane >> 2);
#pragma unroll
        for (int r4 = 0; r4 < 4; r4++) {
            int r = rbase + r4 * 8;
#pragma unroll
            for (int j = 0; j < 8; j++)
                atomicAdd(&g_f8pre[r * NQ + j], part[r4][j]);
        }
    }
}

// ---------------------------------------------------------------------------
// Kernel 2: fused tanh + quantum sim + post MLP. One warp per sample.
// Each block loads weights once and processes QITER sample groups.
// ---------------------------------------------------------------------------
__global__ __launch_bounds__(256, 2)
void qpost_kernel(const float* __restrict__ b2q,
                  const float* __restrict__ W1, const float* __restrict__ b1,
                  const float* __restrict__ W2, const float* __restrict__ b2,
                  const float* __restrict__ W3, const float* __restrict__ b3,
                  float* __restrict__ out) {
    __shared__ float2 gs[NLAYERS * NQ * 4];
    __shared__ float w1s[NQ * HID];
    __shared__ float b1s[HID];
    __shared__ float w2s[HID * 64];
    __shared__ float b2s[64];
    __shared__ float w3s[64 * NACT];
    __shared__ float b3s[NACT];
    __shared__ float b2qs[NQ];
    __shared__ float h2s[8][HID];
    __shared__ float h3s[8][64];

    const int tid = threadIdx.x;
    const int warp = tid >> 5, lane = tid & 31;
    if (tid < NLAYERS * NQ * 4) gs[tid] = g_gates[tid];
    for (int i = tid; i < NQ * HID; i += 256) w1s[i] = W1[i];
    if (tid < HID) b1s[tid] = b1[tid];
    for (int i = tid; i < HID * 64; i += 256) w2s[i] = W2[i];
    if (tid < 64) b2s[tid] = b2[tid];
    for (int i = tid; i < 64 * NACT; i += 256) w3s[i] = W3[i];
    if (tid < NACT) b3s[tid] = b3[tid];
    if (tid < NQ) b2qs[tid] = b2q[tid];
    __syncthreads();

    for (int it = 0; it < QITER; it++) {
        const int b = (blockIdx.x + it * QBLOCKS) * 8 + warp;

        // feats8 = tanh(g_f8pre + b2q)
        float f = tanhf(g_f8pre[b * NQ + (lane & 7)] + b2qs[lane & 7]);
        float a0[NQ], a1[NQ];
#pragma unroll
        for (int i = 0; i < NQ; i++) {
            float th = __shfl_sync(0xffffffffu, f, i) * 1.57079632679489662f;
            float s, c;
            sincosf(th, &s, &c);
            const float r = 0.70710678118654752f;
            a0[i] = (c - s) * r;
            a1[i] = (c + s) * r;
        }
        float2 a[8];
#pragma unroll
        for (int r8 = 0; r8 < 8; r8++) {
            int idx = (r8 << 5) | lane;
            float p = 1.f;
#pragma unroll
            for (int i = 0; i < NQ; i++)
                p *= ((idx >> (7 - i)) & 1) ? a1[i] : a0[i];
            a[r8] = make_float2(p, 0.f);
        }

#pragma unroll 1
        for (int layer = 0; layer < NLAYERS; layer++) {
            { float2 t = a[4]; a[4] = a[6]; a[6] = t;
              t = a[5]; a[5] = a[7]; a[7] = t; }
#pragma unroll
            for (int r8 = 1; r8 < 8; r8 += 2) BFLY2(a[r8], 16);
            { bool cb = (lane >> 3) & 1;
#pragma unroll
              for (int r8 = 0; r8 < 8; r8++) {
                  float2 t = a[r8]; BFLY2(t, 4); if (cb) a[r8] = t;
              } }
            { bool cb = (lane >> 1) & 1;
#pragma unroll
              for (int r8 = 0; r8 < 8; r8++) {
                  float2 t = a[r8]; BFLY2(t, 1); if (cb) a[r8] = t;
              } }
            { float2 t = a[2]; a[2] = a[3]; a[3] = t;
              t = a[6]; a[6] = a[7]; a[7] = t; }
            { bool cb = (lane >> 4) & 1;
#pragma unroll
              for (int r8 = 0; r8 < 8; r8++) {
                  float2 t = a[r8]; BFLY2(t, 8); if (cb) a[r8] = t;
              } }
            { bool cb = (lane >> 2) & 1;
#pragma unroll
              for (int r8 = 0; r8 < 8; r8++) {
                  float2 t = a[r8]; BFLY2(t, 2); if (cb) a[r8] = t;
              } }

            const float2* gl = &gs[layer * NQ * 4];
#pragma unroll
            for (int i = 0; i < NQ; i++) {
                const int p = 7 - i;
                float2 g0 = gl[i * 4 + 0], g1 = gl[i * 4 + 1];
                float2 g2 = gl[i * 4 + 2], g3 = gl[i * 4 + 3];
                if (p >= 5) {
                    const int rb = 1 << (p - 5);
#pragma unroll
                    for (int r0 = 0; r0 < 8; r0++) {
                        if (r0 & rb) continue;
                        int r1 = r0 | rb;
                        float2 x = a[r0], y = a[r1];
                        a[r0] = cmadd2(g0, x, g1, y);
                        a[r1] = cmadd2(g2, x, g3, y);
                    }
                } else {
                    const int mask = 1 << p;
                    const int bit = (lane >> p) & 1;
                    float2 ga = bit ? g3 : g0;
                    float2 gb = bit ? g2 : g1;
#pragma unroll
                    for (int r8 = 0; r8 < 8; r8++) {
                        float2 o = a[r8]; BFLY2(o, mask);
                        a[r8] = cmadd2(ga, a[r8], gb, o);
                    }
                }
            }
        }

        // Measurement
        float pr[8];
#pragma unroll
        for (int r8 = 0; r8 < 8; r8++)
            pr[r8] = a[r8].x * a[r8].x + a[r8].y * a[r8].y;

        float ev[NQ];
        ev[0] = pr[0] + pr[1] + pr[2] + pr[3] - pr[4] - pr[5] - pr[6] - pr[7];
        ev[1] = pr[0] + pr[1] - pr[2] - pr[3] + pr[4] + pr[5] - pr[6] - pr[7];
        ev[2] = pr[0] - pr[1] + pr[2] - pr[3] + pr[4] - pr[5] + pr[6] - pr[7];
        float T = pr[0] + pr[1] + pr[2] + pr[3] + pr[4] + pr[5] + pr[6] + pr[7];
#pragma unroll
        for (int i = 3; i < NQ; i++) {
            int p = 7 - i;
            ev[i] = ((lane >> p) & 1) ? -T : T;
        }
#pragma unroll
        for (int off = 16; off > 0; off >>= 1)
#pragma unroll
            for (int i = 0; i < NQ; i++)
                ev[i] += __shfl_xor_sync(0xffffffffu, ev[i], off);

        // Post MLP directly on ev (broadcast across lanes)
#pragma unroll
        for (int jj = 0; jj < 4; jj++) {
            int j = lane + jj * 32;
            float s = b1s[j];
#pragma unroll
            for (int i = 0; i < NQ; i++) s = fmaf(ev[i], w1s[i * HID + j], s);
            h2s[warp][j] = fmaxf(s, 0.f);
        }
        __syncwarp();

#pragma unroll
        for (int jj = 0; jj < 2; jj++) {
            int j = lane + jj * 32;
            float s = b2s[j];
#pragma unroll
            for (int k = 0; k < HID; k++)
                s = fmaf(h2s[warp][k], w2s[k * 64 + j], s);
            h3s[warp][j] = fmaxf(s, 0.f);
        }
        __syncwarp();

        if (lane < NACT) {
            float s = b3s[lane];
#pragma unroll
            for (int k = 0; k < 64; k++)
                s = fmaf(h3s[warp][k], w3s[k * NACT + lane], s);
            out[b * NACT + lane] = s;
        }
        __syncwarp();
    }
}

// ---------------------------------------------------------------------------
// Launcher
// ---------------------------------------------------------------------------
extern "C" void kernel_launch(void* const* d_in, const int* in_sizes, int n_in,
                              void* d_out, int out_size) {
    const float* x       = (const float*)d_in[0];
    const float* pre_W1  = (const float*)d_in[1];
    const float* pre_b1  = (const float*)d_in[2];
    const float* pre_W2  = (const float*)d_in[3];
    const float* pre_b2  = (const float*)d_in[4];
    const float* qparams = (const float*)d_in[5];
    const float* post_W1 = (const float*)d_in[6];
    const float* post_b1 = (const float*)d_in[7];
    const float* post_W2 = (const float*)d_in[8];
    const float* post_b2 = (const float*)d_in[9];
    const float* post_W3 = (const float*)d_in[10];
    const float* post_b3 = (const float*)d_in[11];
    float* out = (float*)d_out;

    static int init_done = 0;
    static void* f8_addr = nullptr;
    if (!init_done) {
        cudaFuncSetAttribute(gemm1_mma_kernel,
                             cudaFuncAttributeMaxDynamicSharedMemorySize, SMEM_G);
        cudaGetSymbolAddress(&f8_addr, g_f8pre);
        init_done = 1;
    }

    fuse_gates_kernel<<<1, 32>>>(qparams);
    convert_x_kernel<<<B_SZ, 256>>>(x);
    convert_w_kernel<<<dim3(KPAD / 32, H1 / 32), dim3(32, 8)>>>(pre_W1);
    cudaMemsetAsync(f8_addr, 0, B_SZ * NQ * sizeof(float));

    gemm1_mma_kernel<<<dim3(2, 64), 512, SMEM_G>>>(pre_b1, pre_W2);

    qpost_kernel<<<QBLOCKS, 256>>>(pre_b2, post_W1, post_b1, post_W2, post_b2,
                                   post_W3, post_b3, out);
}

// round 16
// speedup vs baseline: 1.0497x; 1.0306x over previous
#include <cuda_runtime.h>
#include <cuda_fp16.h>
#include <math.h>
#include <stdint.h>

// ---------------------------------------------------------------------------
// Problem constants
// ---------------------------------------------------------------------------
#define B_SZ      8192
#define IN_DIM    7056
#define KPAD      7104
#define NC        222          // chunks of 32 (KPAD/32; X padded with zeros)
#define H1        512
#define FEAT      256
#define NQ        8
#define NLAYERS   3
#define HID       128
#define NACT      6

// GEMM1: two independent 8-warp groups per CTA, each 128x128 output tile.
// fp16 2-pass split:  D = X16*Whi + X16*Wlo  (fp32 accumulate)
// Per-group stage: [A 8K][Bhi 8K][Blo 8K] = 24KB, 4 stages.
#define BM        128
#define BN        256
#define BK        32
#define ROWB      64
#define STG       24576
#define NSTAGE    4
#define GRP       (NSTAGE * STG)  // 98304 per group
#define W2OFF     (2 * GRP)       // 196608
#define SMEM_G    (W2OFF + 8192)  // 204800

// prep kernel block ranges
#define WBLKS     (222 * 16)      // convert_w blocks
#define PREP_GRID (B_SZ + WBLKS + 1)

// ---------------------------------------------------------------------------
// Device scratch (no allocations allowed)
// ---------------------------------------------------------------------------
__device__ float  g_f8pre[B_SZ * NQ];             // pre-tanh feats8 accumulator
__device__ float2 g_gates[NLAYERS * NQ * 4];      // fused RZ*RY*RX
__device__ __half g_xh[(size_t)B_SZ * KPAD];      // X in fp16
__device__ __half g_wthi[(size_t)H1 * KPAD];      // W^T hi: [n][k]
__device__ __half g_wtlo[(size_t)H1 * KPAD];      // W^T lo

// ---------------------------------------------------------------------------
// Helpers
// ---------------------------------------------------------------------------
__device__ __forceinline__ float2 cmul(float2 a, float2 b) {
    return make_float2(a.x * b.x - a.y * b.y, a.x * b.y + a.y * b.x);
}
__device__ __forceinline__ float2 cmadd2(float2 ga, float2 x, float2 gb, float2 y) {
    float re = ga.x * x.x - ga.y * x.y + gb.x * y.x - gb.y * y.y;
    float im = ga.x * x.y + ga.y * x.x + gb.x * y.y + gb.y * y.x;
    return make_float2(re, im);
}

__device__ __forceinline__ uint32_t s2u(const void* p) {
    uint32_t a;
    asm("{ .reg .u64 t; cvta.to.shared.u64 t, %1; cvt.u32.u64 %0, t; }"
        : "=r"(a) : "l"(p));
    return a;
}

__device__ __forceinline__ void ldsm_x4(uint32_t* r, uint32_t addr) {
    asm volatile("ldmatrix.sync.aligned.m8n8.x4.shared.b16 {%0,%1,%2,%3}, [%4];"
        : "=r"(r[0]), "=r"(r[1]), "=r"(r[2]), "=r"(r[3]) : "r"(addr));
}

__device__ __forceinline__ void mma_f16(float* c, const uint32_t* a,
                                        const uint32_t* b) {
    asm volatile(
        "mma.sync.aligned.m16n8k16.row.col.f32.f16.f16.f32 "
        "{%0,%1,%2,%3},{%4,%5,%6,%7},{%8,%9},{%0,%1,%2,%3};"
        : "+f"(c[0]), "+f"(c[1]), "+f"(c[2]), "+f"(c[3])
        : "r"(a[0]), "r"(a[1]), "r"(a[2]), "r"(a[3]), "r"(b[0]), "r"(b[1]));
}

#define BFLY2(v, m) do { \
    (v).x = __shfl_xor_sync(0xffffffffu, (v).x, (m)); \
    (v).y = __shfl_xor_sync(0xffffffffu, (v).y, (m)); \
} while (0)

// ---------------------------------------------------------------------------
// prep kernel: one launch does X->fp16 (+ f8pre zeroing), W->fp16 hi/lo
// transposed, and gate fusion, dispatched on blockIdx ranges.
// ---------------------------------------------------------------------------
__global__ __launch_bounds__(256)
void prep_kernel(const float* __restrict__ X, const float* __restrict__ W,
                 const float* __restrict__ qp) {
    const int bid = blockIdx.x;
    const int tid = threadIdx.x;

    if (bid < B_SZ) {
        // ---- convert X row bid, zero g_f8pre row bid ----
        if (tid < NQ) g_f8pre[bid * NQ + tid] = 0.f;
        const float4* src = (const float4*)(X + (size_t)bid * IN_DIM);
        __half2* dst = (__half2*)(g_xh + (size_t)bid * KPAD);
        for (int k4 = tid; k4 < KPAD / 4; k4 += 256) {
            float4 v = (k4 < IN_DIM / 4) ? src[k4]
                                         : make_float4(0.f, 0.f, 0.f, 0.f);
            dst[k4 * 2 + 0] = __floats2half2_rn(v.x, v.y);
            dst[k4 * 2 + 1] = __floats2half2_rn(v.z, v.w);
        }
    } else if (bid < B_SZ + WBLKS) {
        // ---- convert_w tile ----
        __shared__ float t[32][33];
        const int i = bid - B_SZ;
        const int k0 = (i % 222) * 32, n0 = (i / 222) * 32;
        const int tx = tid & 31, ty = tid >> 5;   // 32 x 8
#pragma unroll
        for (int r = 0; r < 32; r += 8) {
            int k = k0 + ty + r;
            t[ty + r][tx] = (k < IN_DIM) ? W[(size_t)k * H1 + n0 + tx] : 0.f;
        }
        __syncthreads();
#pragma unroll
        for (int r = 0; r < 32; r += 8) {
            int n = n0 + ty + r;
            int k = k0 + tx;
            float v = t[tx][ty + r];
            __half h = __float2half_rn(v);
            g_wthi[(size_t)n * KPAD + k] = h;
            g_wtlo[(size_t)n * KPAD + k] = __float2half_rn(v - __half2float(h));
        }
    } else {
        // ---- fuse gates ----
        if (tid >= NLAYERS * NQ) return;
        float a = qp[tid * 3 + 0], b = qp[tid * 3 + 1], c = qp[tid * 3 + 2];
        float sa, ca, sb, cb, sc, cc;
        sincosf(0.5f * a, &sa, &ca);
        sincosf(0.5f * b, &sb, &cb);
        sincosf(0.5f * c, &sc, &cc);
        float2 m00 = make_float2( cb * ca,  sb * sa);
        float2 m01 = make_float2(-sb * ca, -cb * sa);
        float2 m10 = make_float2( sb * ca, -cb * sa);
        float2 m11 = make_float2( cb * ca, -sb * sa);
        float2 e0 = make_float2(cc, -sc);
        float2 e1 = make_float2(cc,  sc);
        g_gates[tid * 4 + 0] = cmul(e0, m00);
        g_gates[tid * 4 + 1] = cmul(e0, m01);
        g_gates[tid * 4 + 2] = cmul(e1, m10);
        g_gates[tid * 4 + 3] = cmul(e1, m11);
    }
}

// ---------------------------------------------------------------------------
// GEMM1: mma.sync fp16 2-pass (X*Whi + X*Wlo), two decoupled 8-warp groups.
// Each group: 128x128 output, own 4-stage pipeline, own named barrier.
// Fused epilogue: partial feats8 = relu(acc+b1) @ W2[:, :8] -> atomicAdd.
// Swizzled 64B smem rows (slot = c16 ^ ((row>>1)&3)).
// ---------------------------------------------------------------------------
__device__ __forceinline__ uint32_t sw_off(int row, int c16) {
    return (uint32_t)row * ROWB + (uint32_t)((c16 ^ ((row >> 1) & 3)) << 4);
}

__device__ __forceinline__ void load_chunk_g(uint32_t stage, int bm, int bng,
                                             int c, int gtid) {
    const size_t kelem = (size_t)c * BK;
#pragma unroll
    for (int j = 0; j < 2; j++) {         // A: 512 granules (fp16 X)
        int idx = gtid + j * 256;
        int row = idx >> 2, c16 = idx & 3;
        const char* src = (const char*)(g_xh + (size_t)(bm + row) * KPAD + kelem
                                        + c16 * 8);
        uint32_t dst = stage + sw_off(row, c16);
        asm volatile("cp.async.cg.shared.global [%0], [%1], 16;"
                     :: "r"(dst), "l"(src));
    }
#pragma unroll
    for (int j = 0; j < 4; j++) {         // B: 2 splits x 512 granules
        int id = gtid + j * 256;
        int split = id >> 9, idx = id & 511;
        int row = idx >> 2, c16 = idx & 3;
        const __half* base = split ? g_wtlo : g_wthi;
        const char* src = (const char*)(base + (size_t)(bng + row) * KPAD + kelem
                                        + c16 * 8);
        uint32_t dst = stage + 8192u + (uint32_t)split * 8192u + sw_off(row, c16);
        asm volatile("cp.async.cg.shared.global [%0], [%1], 16;"
                     :: "r"(dst), "l"(src));
    }
}

__global__ __launch_bounds__(512, 1)
void gemm1_mma_kernel(const float* __restrict__ bias,
                      const float* __restrict__ W2) {
    extern __shared__ char smem[];
    const uint32_t sb = s2u(smem);
    const int tid = threadIdx.x, wid = tid >> 5, lane = tid & 31;
    const int g = wid >> 3;               // group 0/1
    const int gtid = tid & 255;
    const uint32_t gbase = sb + (uint32_t)g * GRP;
    const int bm = blockIdx.y * BM;
    const int bng = blockIdx.x * BN + g * 128;
    const int wg = wid & 7;
    const int wm = (wg >> 1) * 32;        // warp row within group tile
    const int wn = (wg & 1) * 64;         // warp col within group tile
    const int barid = g + 1;

    // Each group loads its own W2 slice [128][8] (visible after first bar.sync)
    {
        float* w2s = (float*)(smem + W2OFF) + g * 1024;
        for (int i = gtid; i < 1024; i += 256) {
            int kk = i >> 3, j = i & 7;
            w2s[i] = W2[(size_t)(bng + kk) * FEAT + j];
        }
    }

    float acc[2][8][4];
#pragma unroll
    for (int mt = 0; mt < 2; mt++)
#pragma unroll
        for (int nt = 0; nt < 8; nt++)
#pragma unroll
            for (int q = 0; q < 4; q++) acc[mt][nt][q] = 0.f;

    // prologue: chunks 0,1 into stages 0,1
    load_chunk_g(gbase + 0 * STG, bm, bng, 0, gtid);
    asm volatile("cp.async.commit_group;" ::: "memory");
    load_chunk_g(gbase + 1 * STG, bm, bng, 1, gtid);
    asm volatile("cp.async.commit_group;" ::: "memory");

    const int lr = lane & 15;
    const int lc = lane >> 4;

    for (int c = 0; c < NC; c++) {
        asm volatile("cp.async.wait_group 1;" ::: "memory");
        asm volatile("bar.sync %0, %1;" :: "r"(barid), "r"(256) : "memory");
        if (c + 2 < NC)
            load_chunk_g(gbase + (uint32_t)((c + 2) & 3) * STG, bm, bng,
                         c + 2, gtid);
        asm volatile("cp.async.commit_group;" ::: "memory");

        const uint32_t aBase = gbase + (uint32_t)(c & 3) * STG;
        const uint32_t bBase = aBase + 8192u;
#pragma unroll
        for (int kk = 0; kk < 2; kk++) {
            const int c16 = kk * 2 + lc;
            uint32_t ah[8], bh[16];
#pragma unroll
            for (int mt = 0; mt < 2; mt++)
                ldsm_x4(&ah[mt * 4], aBase + sw_off(wm + mt * 16 + lr, c16));
#pragma unroll
            for (int bt = 0; bt < 4; bt++)
                ldsm_x4(&bh[bt * 4], bBase + sw_off(wn + bt * 16 + lr, c16));
            // pass 1: X * Whi
#pragma unroll
            for (int mt = 0; mt < 2; mt++)
#pragma unroll
                for (int nt = 0; nt < 8; nt++) {
                    uint32_t bp[2] = { bh[(nt >> 1) * 4 + (nt & 1)],
                                       bh[(nt >> 1) * 4 + 2 + (nt & 1)] };
                    mma_f16(acc[mt][nt], &ah[mt * 4], bp);
                }
            // pass 2: X * Wlo
            {
                uint32_t bl[16];
#pragma unroll
                for (int bt = 0; bt < 4; bt++)
                    ldsm_x4(&bl[bt * 4], bBase + 8192u
                                         + sw_off(wn + bt * 16 + lr, c16));
#pragma unroll
                for (int mt = 0; mt < 2; mt++)
#pragma unroll
                    for (int nt = 0; nt < 8; nt++) {
                        uint32_t bp[2] = { bl[(nt >> 1) * 4 + (nt & 1)],
                                           bl[(nt >> 1) * 4 + 2 + (nt & 1)] };
                        mma_f16(acc[mt][nt], &ah[mt * 4], bp);
                    }
            }
        }
    }

    // Fused epilogue: partial feats8 = relu(acc+bias) @ W2slice -> atomicAdd
    {
        const float* w2l = (const float*)(smem + W2OFF) + g * 1024;
        const int colL = wn + (lane & 3) * 2;
        float part[4][8];
#pragma unroll
        for (int r4 = 0; r4 < 4; r4++)
#pragma unroll
            for (int j = 0; j < 8; j++) part[r4][j] = 0.f;

#pragma unroll
        for (int nt = 0; nt < 8; nt++) {
            int c0 = colL + nt * 8;
            float2 bv = *(const float2*)(bias + bng + c0);
            float4 wa = *(const float4*)(w2l + c0 * 8);
            float4 wb = *(const float4*)(w2l + c0 * 8 + 4);
            float4 wc = *(const float4*)(w2l + (c0 + 1) * 8);
            float4 wd = *(const float4*)(w2l + (c0 + 1) * 8 + 4);
#pragma unroll
            for (int mt = 0; mt < 2; mt++) {
                float h0 = fmaxf(acc[mt][nt][0] + bv.x, 0.f);
                float h1 = fmaxf(acc[mt][nt][1] + bv.y, 0.f);
                float h2 = fmaxf(acc[mt][nt][2] + bv.x, 0.f);
                float h3 = fmaxf(acc[mt][nt][3] + bv.y, 0.f);
                float* p0 = part[mt * 2 + 0];
                float* p1 = part[mt * 2 + 1];
                p0[0] += h0 * wa.x + h1 * wc.x;
                p0[1] += h0 * wa.y + h1 * wc.y;
                p0[2] += h0 * wa.z + h1 * wc.z;
                p0[3] += h0 * wa.w + h1 * wc.w;
                p0[4] += h0 * wb.x + h1 * wd.x;
                p0[5] += h0 * wb.y + h1 * wd.y;
                p0[6] += h0 * wb.z + h1 * wd.z;
                p0[7] += h0 * wb.w + h1 * wd.w;
                p1[0] += h2 * wa.x + h3 * wc.x;
                p1[1] += h2 * wa.y + h3 * wc.y;
                p1[2] += h2 * wa.z + h3 * wc.z;
                p1[3] += h2 * wa.w + h3 * wc.w;
                p1[4] += h2 * wb.x + h3 * wd.x;
                p1[5] += h2 * wb.y + h3 * wd.y;
                p1[6] += h2 * wb.z + h3 * wd.z;
                p1[7] += h2 * wb.w + h3 * wd.w;
            }
        }
        const int rbase = bm + wm + (lane >> 2);
#pragma unroll
        for (int r4 = 0; r4 < 4; r4++) {
            int r = rbase + r4 * 8;
#pragma unroll
            for (int j = 0; j < 8; j++)
                atomicAdd(&g_f8pre[r * NQ + j], part[r4][j]);
        }
    }
}

// ---------------------------------------------------------------------------
// Kernel 2: fused tanh + quantum sim + post MLP. One warp per sample.
// ---------------------------------------------------------------------------
__global__ __launch_bounds__(256, 2)
void qpost_kernel(const float* __restrict__ b2q,
                  const float* __restrict__ W1, const float* __restrict__ b1,
                  const float* __restrict__ W2, const float* __restrict__ b2,
                  const float* __restrict__ W3, const float* __restrict__ b3,
                  float* __restrict__ out) {
    __shared__ float2 gs[NLAYERS * NQ * 4];
    __shared__ float w1s[NQ * HID];
    __shared__ float b1s[HID];
    __shared__ float w2s[HID * 64];
    __shared__ float b2s[64];
    __shared__ float w3s[64 * NACT];
    __shared__ float b3s[NACT];
    __shared__ float h2s[8][HID];
    __shared__ float h3s[8][64];

    const int tid = threadIdx.x;
    const int warp = tid >> 5, lane = tid & 31;
    if (tid < NLAYERS * NQ * 4) gs[tid] = g_gates[tid];
    for (int i = tid; i < NQ * HID; i += 256) w1s[i] = W1[i];
    if (tid < HID) b1s[tid] = b1[tid];
    for (int i = tid; i < HID * 64; i += 256) w2s[i] = W2[i];
    if (tid < 64) b2s[tid] = b2[tid];
    for (int i = tid; i < 64 * NACT; i += 256) w3s[i] = W3[i];
    if (tid < NACT) b3s[tid] = b3[tid];
    __syncthreads();

    const int b = blockIdx.x * 8 + warp;

    // feats8 = tanh(g_f8pre + b2q)
    float f = tanhf(g_f8pre[b * NQ + (lane & 7)] + b2q[lane & 7]);
    float a0[NQ], a1[NQ];
#pragma unroll
    for (int i = 0; i < NQ; i++) {
        float th = __shfl_sync(0xffffffffu, f, i) * 1.57079632679489662f;
        float s, c;
        sincosf(th, &s, &c);
        const float r = 0.70710678118654752f;
        a0[i] = (c - s) * r;
        a1[i] = (c + s) * r;
    }
    float2 a[8];
#pragma unroll
    for (int r8 = 0; r8 < 8; r8++) {
        int idx = (r8 << 5) | lane;
        float p = 1.f;
#pragma unroll
        for (int i = 0; i < NQ; i++)
            p *= ((idx >> (7 - i)) & 1) ? a1[i] : a0[i];
        a[r8] = make_float2(p, 0.f);
    }

#pragma unroll 1
    for (int layer = 0; layer < NLAYERS; layer++) {
        { float2 t = a[4]; a[4] = a[6]; a[6] = t;
          t = a[5]; a[5] = a[7]; a[7] = t; }
#pragma unroll
        for (int r8 = 1; r8 < 8; r8 += 2) BFLY2(a[r8], 16);
        { bool cb = (lane >> 3) & 1;
#pragma unroll
          for (int r8 = 0; r8 < 8; r8++) {
              float2 t = a[r8]; BFLY2(t, 4); if (cb) a[r8] = t;
          } }
        { bool cb = (lane >> 1) & 1;
#pragma unroll
          for (int r8 = 0; r8 < 8; r8++) {
              float2 t = a[r8]; BFLY2(t, 1); if (cb) a[r8] = t;
          } }
        { float2 t = a[2]; a[2] = a[3]; a[3] = t;
          t = a[6]; a[6] = a[7]; a[7] = t; }
        { bool cb = (lane >> 4) & 1;
#pragma unroll
          for (int r8 = 0; r8 < 8; r8++) {
              float2 t = a[r8]; BFLY2(t, 8); if (cb) a[r8] = t;
          } }
        { bool cb = (lane >> 2) & 1;
#pragma unroll
          for (int r8 = 0; r8 < 8; r8++) {
              float2 t = a[r8]; BFLY2(t, 2); if (cb) a[r8] = t;
          } }

        const float2* gl = &gs[layer * NQ * 4];
#pragma unroll
        for (int i = 0; i < NQ; i++) {
            const int p = 7 - i;
            float2 g0 = gl[i * 4 + 0], g1 = gl[i * 4 + 1];
            float2 g2 = gl[i * 4 + 2], g3 = gl[i * 4 + 3];
            if (p >= 5) {
                const int rb = 1 << (p - 5);
#pragma unroll
                for (int r0 = 0; r0 < 8; r0++) {
                    if (r0 & rb) continue;
                    int r1 = r0 | rb;
                    float2 x = a[r0], y = a[r1];
                    a[r0] = cmadd2(g0, x, g1, y);
                    a[r1] = cmadd2(g2, x, g3, y);
                }
            } else {
                const int mask = 1 << p;
                const int bit = (lane >> p) & 1;
                float2 ga = bit ? g3 : g0;
                float2 gb = bit ? g2 : g1;
#pragma unroll
                for (int r8 = 0; r8 < 8; r8++) {
                    float2 o = a[r8]; BFLY2(o, mask);
                    a[r8] = cmadd2(ga, a[r8], gb, o);
                }
            }
        }
    }

    // Measurement
    float pr[8];
#pragma unroll
    for (int r8 = 0; r8 < 8; r8++) pr[r8] = a[r8].x * a[r8].x + a[r8].y * a[r8].y;

    float ev[NQ];
    ev[0] = pr[0] + pr[1] + pr[2] + pr[3] - pr[4] - pr[5] - pr[6] - pr[7];
    ev[1] = pr[0] + pr[1] - pr[2] - pr[3] + pr[4] + pr[5] - pr[6] - pr[7];
    ev[2] = pr[0] - pr[1] + pr[2] - pr[3] + pr[4] - pr[5] + pr[6] - pr[7];
    float T = pr[0] + pr[1] + pr[2] + pr[3] + pr[4] + pr[5] + pr[6] + pr[7];
#pragma unroll
    for (int i = 3; i < NQ; i++) {
        int p = 7 - i;
        ev[i] = ((lane >> p) & 1) ? -T : T;
    }
#pragma unroll
    for (int off = 16; off > 0; off >>= 1)
#pragma unroll
        for (int i = 0; i < NQ; i++)
            ev[i] += __shfl_xor_sync(0xffffffffu, ev[i], off);

    // Post MLP directly on ev (broadcast across lanes)
#pragma unroll
    for (int jj = 0; jj < 4; jj++) {
        int j = lane + jj * 32;
        float s = b1s[j];
#pragma unroll
        for (int i = 0; i < NQ; i++) s = fmaf(ev[i], w1s[i * HID + j], s);
        h2s[warp][j] = fmaxf(s, 0.f);
    }
    __syncwarp();

#pragma unroll
    for (int jj = 0; jj < 2; jj++) {
        int j = lane + jj * 32;
        float s = b2s[j];
#pragma unroll
        for (int k = 0; k < HID; k++) s = fmaf(h2s[warp][k], w2s[k * 64 + j], s);
        h3s[warp][j] = fmaxf(s, 0.f);
    }
    __syncwarp();

    // W3 layer: 24 lanes, each does 16 k's for one of 6 outputs, quad-reduce.
    {
        int j = (lane < 24) ? (lane >> 2) : 0;
        int k0 = (lane & 3) * 16;
        float s = 0.f;
#pragma unroll
        for (int k = 0; k < 16; k++)
            s = fmaf(h3s[warp][k0 + k], w3s[(k0 + k) * NACT + j], s);
        s += __shfl_xor_sync(0xffffffffu, s, 1);
        s += __shfl_xor_sync(0xffffffffu, s, 2);
        if (lane < 24 && (lane & 3) == 0)
            out[b * NACT + j] = s + b3s[j];
    }
}

// ---------------------------------------------------------------------------
// Launcher
// ---------------------------------------------------------------------------
extern "C" void kernel_launch(void* const* d_in, const int* in_sizes, int n_in,
                              void* d_out, int out_size) {
    const float* x       = (const float*)d_in[0];
    const float* pre_W1  = (const float*)d_in[1];
    const float* pre_b1  = (const float*)d_in[2];
    const float* pre_W2  = (const float*)d_in[3];
    const float* pre_b2  = (const float*)d_in[4];
    const float* qparams = (const float*)d_in[5];
    const float* post_W1 = (const float*)d_in[6];
    const float* post_b1 = (const float*)d_in[7];
    const float* post_W2 = (const float*)d_in[8];
    const float* post_b2 = (const float*)d_in[9];
    const float* post_W3 = (const float*)d_in[10];
    const float* post_b3 = (const float*)d_in[11];
    float* out = (float*)d_out;

    static int init_done = 0;
    if (!init_done) {
        cudaFuncSetAttribute(gemm1_mma_kernel,
                             cudaFuncAttributeMaxDynamicSharedMemorySize, SMEM_G);
        init_done = 1;
    }

    prep_kernel<<<PREP_GRID, 256>>>(x, pre_W1, qparams);

    gemm1_mma_kernel<<<dim3(2, 64), 512, SMEM_G>>>(pre_b1, pre_W2);

    qpost_kernel<<<B_SZ / 8, 256>>>(pre_b2, post_W1, post_b1, post_W2, post_b2,
                                    post_W3, post_b3, out);
}

// round 17
// speedup vs baseline: 1.5774x; 1.5027x over previous
#include <cuda_runtime.h>
#include <cuda_fp16.h>
#include <math.h>
#include <stdint.h>

// ---------------------------------------------------------------------------
// Problem constants
// ---------------------------------------------------------------------------
#define B_SZ      8192
#define IN_DIM    7056
#define KPAD      7104
#define NC        222          // chunks of 32 (KPAD/32; X padded with zeros)
#define H1        512
#define FEAT      256
#define NQ        8
#define NLAYERS   3
#define HID       128
#define NACT      6

// GEMM1: two independent 8-warp groups per CTA, each 128x128 output tile.
// fp16 1-pass:  D = X16 * W16  (fp32 accumulate)
// Per-group stage: [A 8K][B 8K] = 16KB, 4 stages.
#define BM        128
#define BN        256
#define BK        32
#define ROWB      64
#define STG       16384
#define NSTAGE    4
#define GRP       (NSTAGE * STG)  // 65536 per group
#define W2OFF     (2 * GRP)       // 131072
#define SMEM_G    (W2OFF + 8192)  // 139264

// prep kernel block ranges
#define WBLKS     (222 * 16)      // convert_w blocks
#define PREP_GRID (B_SZ + WBLKS + 1)

// ---------------------------------------------------------------------------
// Device scratch (no allocations allowed)
// ---------------------------------------------------------------------------
__device__ float  g_f8pre[B_SZ * NQ];             // pre-tanh feats8 accumulator
__device__ float2 g_gates[NLAYERS * NQ * 4];      // fused RZ*RY*RX
__device__ __half g_xh[(size_t)B_SZ * KPAD];      // X in fp16
__device__ __half g_wthi[(size_t)H1 * KPAD];      // W^T: [n][k] fp16

// ---------------------------------------------------------------------------
// Helpers
// ---------------------------------------------------------------------------
__device__ __forceinline__ float2 cmul(float2 a, float2 b) {
    return make_float2(a.x * b.x - a.y * b.y, a.x * b.y + a.y * b.x);
}
__device__ __forceinline__ float2 cmadd2(float2 ga, float2 x, float2 gb, float2 y) {
    float re = ga.x * x.x - ga.y * x.y + gb.x * y.x - gb.y * y.y;
    float im = ga.x * x.y + ga.y * x.x + gb.x * y.y + gb.y * y.x;
    return make_float2(re, im);
}

__device__ __forceinline__ uint32_t s2u(const void* p) {
    uint32_t a;
    asm("{ .reg .u64 t; cvta.to.shared.u64 t, %1; cvt.u32.u64 %0, t; }"
        : "=r"(a) : "l"(p));
    return a;
}

__device__ __forceinline__ void ldsm_x4(uint32_t* r, uint32_t addr) {
    asm volatile("ldmatrix.sync.aligned.m8n8.x4.shared.b16 {%0,%1,%2,%3}, [%4];"
        : "=r"(r[0]), "=r"(r[1]), "=r"(r[2]), "=r"(r[3]) : "r"(addr));
}

__device__ __forceinline__ void mma_f16(float* c, const uint32_t* a,
                                        const uint32_t* b) {
    asm volatile(
        "mma.sync.aligned.m16n8k16.row.col.f32.f16.f16.f32 "
        "{%0,%1,%2,%3},{%4,%5,%6,%7},{%8,%9},{%0,%1,%2,%3};"
        : "+f"(c[0]), "+f"(c[1]), "+f"(c[2]), "+f"(c[3])
        : "r"(a[0]), "r"(a[1]), "r"(a[2]), "r"(a[3]), "r"(b[0]), "r"(b[1]));
}

#define BFLY2(v, m) do { \
    (v).x = __shfl_xor_sync(0xffffffffu, (v).x, (m)); \
    (v).y = __shfl_xor_sync(0xffffffffu, (v).y, (m)); \
} while (0)

// ---------------------------------------------------------------------------
// prep kernel: one launch does X->fp16 (+ f8pre zeroing), W->fp16 transposed,
// and gate fusion, dispatched on blockIdx ranges.
// ---------------------------------------------------------------------------
__global__ __launch_bounds__(256)
void prep_kernel(const float* __restrict__ X, const float* __restrict__ W,
                 const float* __restrict__ qp) {
    const int bid = blockIdx.x;
    const int tid = threadIdx.x;

    if (bid < B_SZ) {
        // ---- convert X row bid, zero g_f8pre row bid ----
        if (tid < NQ) g_f8pre[bid * NQ + tid] = 0.f;
        const float4* src = (const float4*)(X + (size_t)bid * IN_DIM);
        __half2* dst = (__half2*)(g_xh + (size_t)bid * KPAD);
        for (int k4 = tid; k4 < KPAD / 4; k4 += 256) {
            float4 v = (k4 < IN_DIM / 4) ? src[k4]
                                         : make_float4(0.f, 0.f, 0.f, 0.f);
            dst[k4 * 2 + 0] = __floats2half2_rn(v.x, v.y);
            dst[k4 * 2 + 1] = __floats2half2_rn(v.z, v.w);
        }
    } else if (bid < B_SZ + WBLKS) {
        // ---- convert_w tile (transpose, fp16 round-to-nearest) ----
        __shared__ float t[32][33];
        const int i = bid - B_SZ;
        const int k0 = (i % 222) * 32, n0 = (i / 222) * 32;
        const int tx = tid & 31, ty = tid >> 5;   // 32 x 8
#pragma unroll
        for (int r = 0; r < 32; r += 8) {
            int k = k0 + ty + r;
            t[ty + r][tx] = (k < IN_DIM) ? W[(size_t)k * H1 + n0 + tx] : 0.f;
        }
        __syncthreads();
#pragma unroll
        for (int r = 0; r < 32; r += 8) {
            int n = n0 + ty + r;
            int k = k0 + tx;
            g_wthi[(size_t)n * KPAD + k] = __float2half_rn(t[tx][ty + r]);
        }
    } else {
        // ---- fuse gates ----
        if (tid >= NLAYERS * NQ) return;
        float a = qp[tid * 3 + 0], b = qp[tid * 3 + 1], c = qp[tid * 3 + 2];
        float sa, ca, sb, cb, sc, cc;
        sincosf(0.5f * a, &sa, &ca);
        sincosf(0.5f * b, &sb, &cb);
        sincosf(0.5f * c, &sc, &cc);
        float2 m00 = make_float2( cb * ca,  sb * sa);
        float2 m01 = make_float2(-sb * ca, -cb * sa);
        float2 m10 = make_float2( sb * ca, -cb * sa);
        float2 m11 = make_float2( cb * ca, -sb * sa);
        float2 e0 = make_float2(cc, -sc);
        float2 e1 = make_float2(cc,  sc);
        g_gates[tid * 4 + 0] = cmul(e0, m00);
        g_gates[tid * 4 + 1] = cmul(e0, m01);
        g_gates[tid * 4 + 2] = cmul(e1, m10);
        g_gates[tid * 4 + 3] = cmul(e1, m11);
    }
}

// ---------------------------------------------------------------------------
// GEMM1: mma.sync fp16 1-pass (X * W), two decoupled 8-warp groups.
// Each group: 128x128 output, own 4-stage pipeline, own named barrier.
// Fused epilogue: partial feats8 = relu(acc+b1) @ W2[:, :8] -> atomicAdd.
// Swizzled 64B smem rows (slot = c16 ^ ((row>>1)&3)).
// ---------------------------------------------------------------------------
__device__ __forceinline__ uint32_t sw_off(int row, int c16) {
    return (uint32_t)row * ROWB + (uint32_t)((c16 ^ ((row >> 1) & 3)) << 4);
}

__device__ __forceinline__ void load_chunk_g(uint32_t stage, int bm, int bng,
                                             int c, int gtid) {
    const size_t kelem = (size_t)c * BK;
#pragma unroll
    for (int j = 0; j < 2; j++) {         // A: 512 granules (fp16 X)
        int idx = gtid + j * 256;
        int row = idx >> 2, c16 = idx & 3;
        const char* src = (const char*)(g_xh + (size_t)(bm + row) * KPAD + kelem
                                        + c16 * 8);
        uint32_t dst = stage + sw_off(row, c16);
        asm volatile("cp.async.cg.shared.global [%0], [%1], 16;"
                     :: "r"(dst), "l"(src));
    }
#pragma unroll
    for (int j = 0; j < 2; j++) {         // B: 512 granules (fp16 W^T)
        int idx = gtid + j * 256;
        int row = idx >> 2, c16 = idx & 3;
        const char* src = (const char*)(g_wthi + (size_t)(bng + row) * KPAD
                                        + kelem + c16 * 8);
        uint32_t dst = stage + 8192u + sw_off(row, c16);
        asm volatile("cp.async.cg.shared.global [%0], [%1], 16;"
                     :: "r"(dst), "l"(src));
    }
}

__global__ __launch_bounds__(512, 1)
void gemm1_mma_kernel(const float* __restrict__ bias,
                      const float* __restrict__ W2) {
    extern __shared__ char smem[];
    const uint32_t sb = s2u(smem);
    const int tid = threadIdx.x, wid = tid >> 5, lane = tid & 31;
    const int g = wid >> 3;               // group 0/1
    const int gtid = tid & 255;
    const uint32_t gbase = sb + (uint32_t)g * GRP;
    const int bm = blockIdx.y * BM;
    const int bng = blockIdx.x * BN + g * 128;
    const int wg = wid & 7;
    const int wm = (wg >> 1) * 32;        // warp row within group tile
    const int wn = (wg & 1) * 64;         // warp col within group tile
    const int barid = g + 1;

    // Each group loads its own W2 slice [128][8] (visible after first bar.sync)
    {
        float* w2s = (float*)(smem + W2OFF) + g * 1024;
        for (int i = gtid; i < 1024; i += 256) {
            int kk = i >> 3, j = i & 7;
            w2s[i] = W2[(size_t)(bng + kk) * FEAT + j];
        }
    }

    float acc[2][8][4];
#pragma unroll
    for (int mt = 0; mt < 2; mt++)
#pragma unroll
        for (int nt = 0; nt < 8; nt++)
#pragma unroll
            for (int q = 0; q < 4; q++) acc[mt][nt][q] = 0.f;

    // prologue: chunks 0,1 into stages 0,1
    load_chunk_g(gbase + 0 * STG, bm, bng, 0, gtid);
    asm volatile("cp.async.commit_group;" ::: "memory");
    load_chunk_g(gbase + 1 * STG, bm, bng, 1, gtid);
    asm volatile("cp.async.commit_group;" ::: "memory");

    const int lr = lane & 15;
    const int lc = lane >> 4;

    for (int c = 0; c < NC; c++) {
        asm volatile("cp.async.wait_group 1;" ::: "memory");
        asm volatile("bar.sync %0, %1;" :: "r"(barid), "r"(256) : "memory");
        if (c + 2 < NC)
            load_chunk_g(gbase + (uint32_t)((c + 2) & 3) * STG, bm, bng,
                         c + 2, gtid);
        asm volatile("cp.async.commit_group;" ::: "memory");

        const uint32_t aBase = gbase + (uint32_t)(c & 3) * STG;
        const uint32_t bBase = aBase + 8192u;
#pragma unroll
        for (int kk = 0; kk < 2; kk++) {
            const int c16 = kk * 2 + lc;
            uint32_t ah[8], bh[16];
#pragma unroll
            for (int mt = 0; mt < 2; mt++)
                ldsm_x4(&ah[mt * 4], aBase + sw_off(wm + mt * 16 + lr, c16));
#pragma unroll
            for (int bt = 0; bt < 4; bt++)
                ldsm_x4(&bh[bt * 4], bBase + sw_off(wn + bt * 16 + lr, c16));
#pragma unroll
            for (int mt = 0; mt < 2; mt++)
#pragma unroll
                for (int nt = 0; nt < 8; nt++) {
                    uint32_t bp[2] = { bh[(nt >> 1) * 4 + (nt & 1)],
                                       bh[(nt >> 1) * 4 + 2 + (nt & 1)] };
                    mma_f16(acc[mt][nt], &ah[mt * 4], bp);
                }
        }
    }

    // Fused epilogue: partial feats8 = relu(acc+bias) @ W2slice -> atomicAdd
    {
        const float* w2l = (const float*)(smem + W2OFF) + g * 1024;
        const int colL = wn + (lane & 3) * 2;
        float part[4][8];
#pragma unroll
        for (int r4 = 0; r4 < 4; r4++)
#pragma unroll
            for (int j = 0; j < 8; j++) part[r4][j] = 0.f;

#pragma unroll
        for (int nt = 0; nt < 8; nt++) {
            int c0 = colL + nt * 8;
            float2 bv = *(const float2*)(bias + bng + c0);
            float4 wa = *(const float4*)(w2l + c0 * 8);
            float4 wb = *(const float4*)(w2l + c0 * 8 + 4);
            float4 wc = *(const float4*)(w2l + (c0 + 1) * 8);
            float4 wd = *(const float4*)(w2l + (c0 + 1) * 8 + 4);
#pragma unroll
            for (int mt = 0; mt < 2; mt++) {
                float h0 = fmaxf(acc[mt][nt][0] + bv.x, 0.f);
                float h1 = fmaxf(acc[mt][nt][1] + bv.y, 0.f);
                float h2 = fmaxf(acc[mt][nt][2] + bv.x, 0.f);
                float h3 = fmaxf(acc[mt][nt][3] + bv.y, 0.f);
                float* p0 = part[mt * 2 + 0];
                float* p1 = part[mt * 2 + 1];
                p0[0] += h0 * wa.x + h1 * wc.x;
                p0[1] += h0 * wa.y + h1 * wc.y;
                p0[2] += h0 * wa.z + h1 * wc.z;
                p0[3] += h0 * wa.w + h1 * wc.w;
                p0[4] += h0 * wb.x + h1 * wd.x;
                p0[5] += h0 * wb.y + h1 * wd.y;
                p0[6] += h0 * wb.z + h1 * wd.z;
                p0[7] += h0 * wb.w + h1 * wd.w;
                p1[0] += h2 * wa.x + h3 * wc.x;
                p1[1] += h2 * wa.y + h3 * wc.y;
                p1[2] += h2 * wa.z + h3 * wc.z;
                p1[3] += h2 * wa.w + h3 * wc.w;
                p1[4] += h2 * wb.x + h3 * wd.x;
                p1[5] += h2 * wb.y + h3 * wd.y;
                p1[6] += h2 * wb.z + h3 * wd.z;
                p1[7] += h2 * wb.w + h3 * wd.w;
            }
        }
        const int rbase = bm + wm + (lane >> 2);
#pragma unroll
        for (int r4 = 0; r4 < 4; r4++) {
            int r = rbase + r4 * 8;
#pragma unroll
            for (int j = 0; j < 8; j++)
                atomicAdd(&g_f8pre[r * NQ + j], part[r4][j]);
        }
    }
}

// ---------------------------------------------------------------------------
// Kernel 2: fused tanh + quantum sim + post MLP. One warp per sample.
// ---------------------------------------------------------------------------
__global__ __launch_bounds__(256, 2)
void qpost_kernel(const float* __restrict__ b2q,
                  const float* __restrict__ W1, const float* __restrict__ b1,
                  const float* __restrict__ W2, const float* __restrict__ b2,
                  const float* __restrict__ W3, const float* __restrict__ b3,
                  float* __restrict__ out) {
    __shared__ float2 gs[NLAYERS * NQ * 4];
    __shared__ float w1s[NQ * HID];
    __shared__ float b1s[HID];
    __shared__ float w2s[HID * 64];
    __shared__ float b2s[64];
    __shared__ float w3s[64 * NACT];
    __shared__ float b3s[NACT];
    __shared__ float h2s[8][HID];
    __shared__ float h3s[8][64];

    const int tid = threadIdx.x;
    const int warp = tid >> 5, lane = tid & 31;
    if (tid < NLAYERS * NQ * 4) gs[tid] = g_gates[tid];
    for (int i = tid; i < NQ * HID; i += 256) w1s[i] = W1[i];
    if (tid < HID) b1s[tid] = b1[tid];
    for (int i = tid; i < HID * 64; i += 256) w2s[i] = W2[i];
    if (tid < 64) b2s[tid] = b2[tid];
    for (int i = tid; i < 64 * NACT; i += 256) w3s[i] = W3[i];
    if (tid < NACT) b3s[tid] = b3[tid];
    __syncthreads();

    const int b = blockIdx.x * 8 + warp;

    // feats8 = tanh(g_f8pre + b2q)
    float f = tanhf(g_f8pre[b * NQ + (lane & 7)] + b2q[lane & 7]);
    float a0[NQ], a1[NQ];
#pragma unroll
    for (int i = 0; i < NQ; i++) {
        float th = __shfl_sync(0xffffffffu, f, i) * 1.57079632679489662f;
        float s, c;
        sincosf(th, &s, &c);
        const float r = 0.70710678118654752f;
        a0[i] = (c - s) * r;
        a1[i] = (c + s) * r;
    }
    float2 a[8];
#pragma unroll
    for (int r8 = 0; r8 < 8; r8++) {
        int idx = (r8 << 5) | lane;
        float p = 1.f;
#pragma unroll
        for (int i = 0; i < NQ; i++)
            p *= ((idx >> (7 - i)) & 1) ? a1[i] : a0[i];
        a[r8] = make_float2(p, 0.f);
    }

#pragma unroll 1
    for (int layer = 0; layer < NLAYERS; layer++) {
        { float2 t = a[4]; a[4] = a[6]; a[6] = t;
          t = a[5]; a[5] = a[7]; a[7] = t; }
#pragma unroll
        for (int r8 = 1; r8 < 8; r8 += 2) BFLY2(a[r8], 16);
        { bool cb = (lane >> 3) & 1;
#pragma unroll
          for (int r8 = 0; r8 < 8; r8++) {
              float2 t = a[r8]; BFLY2(t, 4); if (cb) a[r8] = t;
          } }
        { bool cb = (lane >> 1) & 1;
#pragma unroll
          for (int r8 = 0; r8 < 8; r8++) {
              float2 t = a[r8]; BFLY2(t, 1); if (cb) a[r8] = t;
          } }
        { float2 t = a[2]; a[2] = a[3]; a[3] = t;
          t = a[6]; a[6] = a[7]; a[7] = t; }
        { bool cb = (lane >> 4) & 1;
#pragma unroll
          for (int r8 = 0; r8 < 8; r8++) {
              float2 t = a[r8]; BFLY2(t, 8); if (cb) a[r8] = t;
          } }
        { bool cb = (lane >> 2) & 1;
#pragma unroll
          for (int r8 = 0; r8 < 8; r8++) {
              float2 t = a[r8]; BFLY2(t, 2); if (cb) a[r8] = t;
          } }

        const float2* gl = &gs[layer * NQ * 4];
#pragma unroll
        for (int i = 0; i < NQ; i++) {
            const int p = 7 - i;
            float2 g0 = gl[i * 4 + 0], g1 = gl[i * 4 + 1];
            float2 g2 = gl[i * 4 + 2], g3 = gl[i * 4 + 3];
            if (p >= 5) {
                const int rb = 1 << (p - 5);
#pragma unroll
                for (int r0 = 0; r0 < 8; r0++) {
                    if (r0 & rb) continue;
                    int r1 = r0 | rb;
                    float2 x = a[r0], y = a[r1];
                    a[r0] = cmadd2(g0, x, g1, y);
                    a[r1] = cmadd2(g2, x, g3, y);
                }
            } else {
                const int mask = 1 << p;
                const int bit = (lane >> p) & 1;
                float2 ga = bit ? g3 : g0;
                float2 gb = bit ? g2 : g1;
#pragma unroll
                for (int r8 = 0; r8 < 8; r8++) {
                    float2 o = a[r8]; BFLY2(o, mask);
                    a[r8] = cmadd2(ga, a[r8], gb, o);
                }
            }
        }
    }

    // Measurement
    float pr[8];
#pragma unroll
    for (int r8 = 0; r8 < 8; r8++) pr[r8] = a[r8].x * a[r8].x + a[r8].y * a[r8].y;

    float ev[NQ];
    ev[0] = pr[0] + pr[1] + pr[2] + pr[3] - pr[4] - pr[5] - pr[6] - pr[7];
    ev[1] = pr[0] + pr[1] - pr[2] - pr[3] + pr[4] + pr[5] - pr[6] - pr[7];
    ev[2] = pr[0] - pr[1] + pr[2] - pr[3] + pr[4] - pr[5] + pr[6] - pr[7];
    float T = pr[0] + pr[1] + pr[2] + pr[3] + pr[4] + pr[5] + pr[6] + pr[7];
#pragma unroll
    for (int i = 3; i < NQ; i++) {
        int p = 7 - i;
        ev[i] = ((lane >> p) & 1) ? -T : T;
    }
#pragma unroll
    for (int off = 16; off > 0; off >>= 1)
#pragma unroll
        for (int i = 0; i < NQ; i++)
            ev[i] += __shfl_xor_sync(0xffffffffu, ev[i], off);

    // Post MLP directly on ev (broadcast across lanes)
#pragma unroll
    for (int jj = 0; jj < 4; jj++) {
        int j = lane + jj * 32;
        float s = b1s[j];
#pragma unroll
        for (int i = 0; i < NQ; i++) s = fmaf(ev[i], w1s[i * HID + j], s);
        h2s[warp][j] = fmaxf(s, 0.f);
    }
    __syncwarp();

#pragma unroll
    for (int jj = 0; jj < 2; jj++) {
        int j = lane + jj * 32;
        float s = b2s[j];
#pragma unroll
        for (int k = 0; k < HID; k++) s = fmaf(h2s[warp][k], w2s[k * 64 + j], s);
        h3s[warp][j] = fmaxf(s, 0.f);
    }
    __syncwarp();

    // W3 layer: 24 lanes, each does 16 k's for one of 6 outputs, quad-reduce.
    {
        int j = (lane < 24) ? (lane >> 2) : 0;
        int k0 = (lane & 3) * 16;
        float s = 0.f;
#pragma unroll
        for (int k = 0; k < 16; k++)
            s = fmaf(h3s[warp][k0 + k], w3s[(k0 + k) * NACT + j], s);
        s += __shfl_xor_sync(0xffffffffu, s, 1);
        s += __shfl_xor_sync(0xffffffffu, s, 2);
        if (lane < 24 && (lane & 3) == 0)
            out[b * NACT + j] = s + b3s[j];
    }
}

// ---------------------------------------------------------------------------
// Launcher
// ---------------------------------------------------------------------------
extern "C" void kernel_launch(void* const* d_in, const int* in_sizes, int n_in,
                              void* d_out, int out_size) {
    const float* x       = (const float*)d_in[0];
    const float* pre_W1  = (const float*)d_in[1];
    const float* pre_b1  = (const float*)d_in[2];
    const float* pre_W2  = (const float*)d_in[3];
    const float* pre_b2  = (const float*)d_in[4];
    const float* qparams = (const float*)d_in[5];
    const float* post_W1 = (const float*)d_in[6];
    const float* post_b1 = (const float*)d_in[7];
    const float* post_W2 = (const float*)d_in[8];
    const float* post_b2 = (const float*)d_in[9];
    const float* post_W3 = (const float*)d_in[10];
    const float* post_b3 = (const float*)d_in[11];
    float* out = (float*)d_out;

    static int init_done = 0;
    if (!init_done) {
        cudaFuncSetAttribute(gemm1_mma_kernel,
                             cudaFuncAttributeMaxDynamicSharedMemorySize, SMEM_G);
        init_done = 1;
    }

    prep_kernel<<<PREP_GRID, 256>>>(x, pre_W1, qparams);

    gemm1_mma_kernel<<<dim3(2, 64), 512, SMEM_G>>>(pre_b1, pre_W2);

    qpost_kernel<<<B_SZ / 8, 256>>>(pre_b2, post_W1, post_b1, post_W2, post_b2,
                                    post_W3, post_b3, out);
}